// round 2
// baseline (speedup 1.0000x reference)
#include <cuda_runtime.h>
#include <cuda_bf16.h>
#include <math.h>

// Problem constants
#define NBATCH 2
#define SEQ    4096
#define EMB    1024
#define FFDIM  4096
#define MROWS  (NBATCH*SEQ)   // 8192 total rows

// GEMM tiling
#define TILE_M 128
#define TILE_N 128
#define TILE_K 16
#define THR_M  8
#define THR_N  8
#define NTHREADS 256

// Scratch (device globals; allocation-free)
__device__ float g_q[MROWS * EMB];
__device__ float g_k[MROWS * EMB];
__device__ float g_v[MROWS * EMB];
__device__ float g_x[MROWS * EMB];      // attn@v result; LN1 in-place
__device__ float g_h[MROWS * FFDIM];    // FFN hidden (also attn fallback scratch)
__device__ float g_y[MROWS * EMB];      // FFN2 out

// EPI: 0 = +bias, 1 = relu(+bias), 2 = sigmoid(acc*scale)
// BT : true  => C = A @ B^T  (B is N x K row-major)
//      false => C = A @ B    (B is K x N row-major)
template<int EPI, bool BT>
__global__ void __launch_bounds__(NTHREADS)
sgemm_kernel(const float* __restrict__ A, const float* __restrict__ A2,
             const float* __restrict__ B, const float* __restrict__ bias,
             float* __restrict__ C,
             int M, int N, int K,
             size_t sA, size_t sB, size_t sC, float scale)
{
    __shared__ float As[TILE_K][TILE_M];
    __shared__ float Bs[TILE_K][TILE_N];

    const int bz = blockIdx.z;
    A += (size_t)bz * sA;
    if (A2) A2 += (size_t)bz * sA;
    B += (size_t)bz * sB;
    C += (size_t)bz * sC;

    const int mBase = blockIdx.y * TILE_M;
    const int nBase = blockIdx.x * TILE_N;
    const int t  = threadIdx.x;
    const int tx = t & 15;   // n-dir (16)
    const int ty = t >> 4;   // m-dir (16)

    float acc[THR_M][THR_N];
    #pragma unroll
    for (int i = 0; i < THR_M; i++)
        #pragma unroll
        for (int j = 0; j < THR_N; j++)
            acc[i][j] = 0.f;

    // loader indices (A and B-transposed use the same pattern)
    const int arow = t >> 2;        // 0..63
    const int acol = (t & 3) * 4;   // 0,4,8,12

    for (int k0 = 0; k0 < K; k0 += TILE_K) {
        // ---- load A tile (128 x 16), store transposed into As[k][m]
        #pragma unroll
        for (int r = 0; r < 2; r++) {
            const int row = arow + r * 64;
            float4 v = *(const float4*)(A + (size_t)(mBase + row) * K + k0 + acol);
            if (A2) {
                const float4 v2 = *(const float4*)(A2 + (size_t)(mBase + row) * K + k0 + acol);
                v.x += v2.x; v.y += v2.y; v.z += v2.z; v.w += v2.w;
            }
            As[acol + 0][row] = v.x;
            As[acol + 1][row] = v.y;
            As[acol + 2][row] = v.z;
            As[acol + 3][row] = v.w;
        }
        // ---- load B tile
        if (BT) {
            #pragma unroll
            for (int r = 0; r < 2; r++) {
                const int row = arow + r * 64;  // n index
                const float4 v = *(const float4*)(B + (size_t)(nBase + row) * K + k0 + acol);
                Bs[acol + 0][row] = v.x;
                Bs[acol + 1][row] = v.y;
                Bs[acol + 2][row] = v.z;
                Bs[acol + 3][row] = v.w;
            }
        } else {
            const int bk = t >> 5;          // 0..7
            const int bn = (t & 31) * 4;    // 0..124
            #pragma unroll
            for (int r = 0; r < 2; r++) {
                const int kk = bk + r * 8;
                *(float4*)&Bs[kk][bn] =
                    *(const float4*)(B + (size_t)(k0 + kk) * N + nBase + bn);
            }
        }
        __syncthreads();

        // ---- compute
        #pragma unroll
        for (int kk = 0; kk < TILE_K; kk++) {
            float ar[THR_M], br[THR_N];
            #pragma unroll
            for (int i = 0; i < THR_M; i++) ar[i] = As[kk][ty * THR_M + i];
            #pragma unroll
            for (int j = 0; j < THR_N; j++) br[j] = Bs[kk][tx * THR_N + j];
            #pragma unroll
            for (int i = 0; i < THR_M; i++)
                #pragma unroll
                for (int j = 0; j < THR_N; j++)
                    acc[i][j] = fmaf(ar[i], br[j], acc[i][j]);
        }
        __syncthreads();
    }

    // ---- epilogue
    float bvals[THR_N];
    #pragma unroll
    for (int j = 0; j < THR_N; j++)
        bvals[j] = (EPI != 2 && bias) ? bias[nBase + tx * THR_N + j] : 0.f;

    #pragma unroll
    for (int i = 0; i < THR_M; i++) {
        const int row = mBase + ty * THR_M + i;
        #pragma unroll
        for (int j = 0; j < THR_N; j++) {
            float v = acc[i][j];
            if (EPI == 0) {
                v += bvals[j];
            } else if (EPI == 1) {
                v += bvals[j];
                v = v > 0.f ? v : 0.f;
            } else { // sigmoid(scale * acc)
                v = 1.f / (1.f + __expf(-v * scale));
            }
            acc[i][j] = v;
        }
        float* cp = C + (size_t)row * N + nBase + tx * THR_N;
        *(float4*)(cp)     = make_float4(acc[i][0], acc[i][1], acc[i][2], acc[i][3]);
        *(float4*)(cp + 4) = make_float4(acc[i][4], acc[i][5], acc[i][6], acc[i][7]);
    }
}

// LayerNorm over last dim E=1024; one block (256 thr) per row; float4 per thread.
__global__ void __launch_bounds__(256)
layernorm_kernel(const float* __restrict__ x, const float* __restrict__ g,
                 const float* __restrict__ b, float* __restrict__ out)
{
    const int row = blockIdx.x;
    const float* xr = x + (size_t)row * EMB;
    float* orow = out + (size_t)row * EMB;
    const int t = threadIdx.x;

    const float4 v = *(const float4*)(xr + t * 4);
    float s  = v.x + v.y + v.z + v.w;
    float ss = v.x * v.x + v.y * v.y + v.z * v.z + v.w * v.w;

    __shared__ float shs[8], shss[8], shmu[1], shinv[1];
    const int lane = t & 31, w = t >> 5;
    #pragma unroll
    for (int o = 16; o > 0; o >>= 1) {
        s  += __shfl_down_sync(0xffffffffu, s,  o);
        ss += __shfl_down_sync(0xffffffffu, ss, o);
    }
    if (lane == 0) { shs[w] = s; shss[w] = ss; }
    __syncthreads();
    if (w == 0) {
        float s2  = (lane < 8) ? shs[lane]  : 0.f;
        float ss2 = (lane < 8) ? shss[lane] : 0.f;
        #pragma unroll
        for (int o = 4; o > 0; o >>= 1) {
            s2  += __shfl_down_sync(0xffffffffu, s2,  o);
            ss2 += __shfl_down_sync(0xffffffffu, ss2, o);
        }
        if (lane == 0) {
            const float mu  = s2 * (1.f / EMB);
            const float var = ss2 * (1.f / EMB) - mu * mu;
            shmu[0]  = mu;
            shinv[0] = rsqrtf(var + 1e-5f);
        }
    }
    __syncthreads();
    const float mu = shmu[0], inv = shinv[0];

    const float4 gv = *(const float4*)(g + t * 4);
    const float4 bv = *(const float4*)(b + t * 4);
    float4 o;
    o.x = (v.x - mu) * inv * gv.x + bv.x;
    o.y = (v.y - mu) * inv * gv.y + bv.y;
    o.z = (v.z - mu) * inv * gv.z + bv.z;
    o.w = (v.w - mu) * inv * gv.w + bv.w;
    *(float4*)(orow + t * 4) = o;
}

extern "C" void kernel_launch(void* const* d_in, const int* in_sizes, int n_in,
                              void* d_out, int out_size)
{
    const float* value  = (const float*)d_in[0];
    const float* key_t  = (const float*)d_in[1];
    const float* query  = (const float*)d_in[2];
    const float* embed0 = (const float*)d_in[3];
    const float* Wq = (const float*)d_in[4];
    const float* bq = (const float*)d_in[5];
    const float* Wk = (const float*)d_in[6];
    const float* bk = (const float*)d_in[7];
    const float* Wv = (const float*)d_in[8];
    const float* bv = (const float*)d_in[9];
    const float* W1 = (const float*)d_in[10];
    const float* b1 = (const float*)d_in[11];
    const float* W2 = (const float*)d_in[12];
    const float* b2 = (const float*)d_in[13];
    const float* g1  = (const float*)d_in[14];
    const float* be1 = (const float*)d_in[15];
    const float* g2  = (const float*)d_in[16];
    const float* be2 = (const float*)d_in[17];

    float *q, *k, *v, *x, *h, *y;
    cudaGetSymbolAddress((void**)&q, g_q);
    cudaGetSymbolAddress((void**)&k, g_k);
    cudaGetSymbolAddress((void**)&v, g_v);
    cudaGetSymbolAddress((void**)&x, g_x);
    cudaGetSymbolAddress((void**)&h, g_h);
    cudaGetSymbolAddress((void**)&y, g_y);

    float* outp = (float*)d_out;
    const long long outElems  = (long long)MROWS * EMB;          // 8388608
    const long long attnElems = (long long)NBATCH * SEQ * SEQ;   // 33554432
    // Output layout: (out, attn) concatenated. If the harness only checks `out`,
    // route attn into scratch (g_h is free until the FFN stage).
    float* attn = ((long long)out_size >= outElems + attnElems) ? (outp + outElems) : h;

    dim3 blk(NTHREADS);
    const float scale = 1.0f / 32.0f;   // 1/sqrt(E)

    // 1) QKV projections, embed-add fused into A-load:  X = (a + embed0) @ W^T + b
    dim3 gQKV(EMB / TILE_N, MROWS / TILE_M, 1);
    sgemm_kernel<0, true><<<gQKV, blk>>>(query, embed0, Wq, bq, q, MROWS, EMB, EMB, 0, 0, 0, 0.f);
    sgemm_kernel<0, true><<<gQKV, blk>>>(key_t, embed0, Wk, bk, k, MROWS, EMB, EMB, 0, 0, 0, 0.f);
    sgemm_kernel<0, true><<<gQKV, blk>>>(value, embed0, Wv, bv, v, MROWS, EMB, EMB, 0, 0, 0, 0.f);

    // 2) attn = sigmoid(q @ k^T * scale)   per-batch [4096 x 4096]
    dim3 gS(SEQ / TILE_N, SEQ / TILE_M, NBATCH);
    sgemm_kernel<2, true><<<gS, blk>>>(q, nullptr, k, nullptr, attn,
                                       SEQ, SEQ, EMB,
                                       (size_t)SEQ * EMB, (size_t)SEQ * EMB, (size_t)SEQ * SEQ, scale);

    // 3) x = attn @ v   (NN gemm)  per-batch [4096 x 1024], K = 4096
    dim3 gAV(EMB / TILE_N, SEQ / TILE_M, NBATCH);
    sgemm_kernel<0, false><<<gAV, blk>>>(attn, nullptr, v, nullptr, x,
                                         SEQ, EMB, SEQ,
                                         (size_t)SEQ * SEQ, (size_t)SEQ * EMB, (size_t)SEQ * EMB, 0.f);

    // 4) LayerNorm 1 (in-place)
    layernorm_kernel<<<MROWS, 256>>>(x, g1, be1, x);

    // 5) FFN1: h = relu(x @ W1^T + b1)   [8192 x 4096], K=1024
    dim3 gF1(FFDIM / TILE_N, MROWS / TILE_M, 1);
    sgemm_kernel<1, true><<<gF1, blk>>>(x, nullptr, W1, b1, h, MROWS, FFDIM, EMB, 0, 0, 0, 0.f);

    // 6) FFN2: y = h @ W2^T + b2         [8192 x 1024], K=4096
    dim3 gF2(EMB / TILE_N, MROWS / TILE_M, 1);
    sgemm_kernel<0, true><<<gF2, blk>>>(h, nullptr, W2, b2, y, MROWS, EMB, FFDIM, 0, 0, 0, 0.f);

    // 7) LayerNorm 2 -> out region of d_out
    layernorm_kernel<<<MROWS, 256>>>(y, g2, be2, outp);
}

// round 4
// speedup vs baseline: 2.2247x; 2.2247x over previous
#include <cuda_runtime.h>
#include <cuda_bf16.h>
#include <cstdint>
#include <math.h>

#define NBATCH 2
#define SEQ    4096
#define EMB    1024
#define FFDIM  4096
#define MROWS  (NBATCH*SEQ)   // 8192

// ---------------- scratch (device globals; allocation-free) ----------------
__device__ float g_q [MROWS * EMB];
__device__ float g_k [MROWS * EMB];
__device__ float g_vt[NBATCH * EMB * SEQ];   // V transposed per batch [E][S]
__device__ float g_x [MROWS * EMB];
__device__ float g_h [MROWS * FFDIM];        // FFN hidden / attn fallback
__device__ float g_y [MROWS * EMB];

// ---------------- helpers ----------------
__device__ __forceinline__ uint32_t smem_u32(const void* p) {
    uint32_t a;
    asm("{ .reg .u64 t; cvta.to.shared.u64 t, %1; cvt.u32.u64 %0, t; }" : "=r"(a) : "l"(p));
    return a;
}
#define SW128(o) (((uint32_t)(o)) ^ ((((uint32_t)(o)) >> 3) & 0x70u))

__device__ __forceinline__ void ldsm4(uint32_t r[4], uint32_t addr) {
    asm volatile("ldmatrix.sync.aligned.m8n8.x4.shared.b16 {%0,%1,%2,%3}, [%4];"
                 : "=r"(r[0]), "=r"(r[1]), "=r"(r[2]), "=r"(r[3]) : "r"(addr));
}
__device__ __forceinline__ void mma16816(float c[4], const uint32_t a[4],
                                         uint32_t b0, uint32_t b1) {
    asm volatile("mma.sync.aligned.m16n8k16.row.col.f32.bf16.bf16.f32 "
                 "{%0,%1,%2,%3}, {%4,%5,%6,%7}, {%8,%9}, {%0,%1,%2,%3};"
                 : "+f"(c[0]), "+f"(c[1]), "+f"(c[2]), "+f"(c[3])
                 : "r"(a[0]), "r"(a[1]), "r"(a[2]), "r"(a[3]), "r"(b0), "r"(b1));
}

// fp32x8 -> bf16 hi/lo, two 16B stores into swizzled SMEM
__device__ __forceinline__ void cvt8_store(uint32_t a_hi, uint32_t a_lo,
                                           const float4& f0, const float4& f1) {
    float xs[8] = {f0.x, f0.y, f0.z, f0.w, f1.x, f1.y, f1.z, f1.w};
    uint32_t H[4], L[4];
    #pragma unroll
    for (int i = 0; i < 4; i++) {
        float a = xs[2*i], b = xs[2*i+1];
        __nv_bfloat162 hp = __floats2bfloat162_rn(a, b);   // .x = a (low half)
        float ha = __bfloat162float(hp.x), hb = __bfloat162float(hp.y);
        __nv_bfloat162 lp = __floats2bfloat162_rn(a - ha, b - hb);
        H[i] = *reinterpret_cast<uint32_t*>(&hp);
        L[i] = *reinterpret_cast<uint32_t*>(&lp);
    }
    asm volatile("st.shared.v4.b32 [%0], {%1,%2,%3,%4};"
                 :: "r"(a_hi), "r"(H[0]), "r"(H[1]), "r"(H[2]), "r"(H[3]) : "memory");
    asm volatile("st.shared.v4.b32 [%0], {%1,%2,%3,%4};"
                 :: "r"(a_lo), "r"(L[0]), "r"(L[1]), "r"(L[2]), "r"(L[3]) : "memory");
}

struct F8 { float4 a, b; };
__device__ __forceinline__ F8 ldg8(const float* p) {
    F8 r; r.a = *(const float4*)p; r.b = *(const float4*)(p + 4); return r;
}

// ---------------- HMMA GEMM: C[M,N] = op( A[M,K] @ B[N,K]^T ) ----------------
// SMEM stage layout: per stage 32KB: A[128 rows][128B = hi(64B)|lo(64B)], then B same.
// EPI: 0 = +bias, 1 = relu(+bias), 2 = sigmoid(acc*scale), 3 = +bias, write V^T
#define STAGE_BYTES 32768
#define EPI_PITCH   132
#define SMEM_TOTAL  (1024 + 2*STAGE_BYTES + 2048)   // also covers epi (128*132*4 = 67584)

template<int EPI>
__global__ void __launch_bounds__(256)
hmma_gemm(const float* __restrict__ A, const float* __restrict__ A2,
          const float* __restrict__ B, const float* __restrict__ bias,
          float* __restrict__ C, int K, int ldC,
          size_t sAs, size_t sBs, size_t sCs, float scale)
{
    extern __shared__ char smem[];
    const uint32_t sb0 = smem_u32(smem);
    const uint32_t sbA = (sb0 + 1023) & ~1023u;   // 1KB-aligned stage base

    const int t = threadIdx.x;
    const int w = t >> 5, lane = t & 31;
    const int wm = w >> 2, wn = w & 3;            // warp grid 2 x 4

    const int bz = blockIdx.z;
    A += (size_t)bz * sAs;
    if (A2) A2 += (size_t)bz * sAs;
    B += (size_t)bz * sBs;
    C += (size_t)bz * sCs;
    const int mBase = blockIdx.y * 128;
    const int nBase = blockIdx.x * 128;

    // staging indices: 2 segments per thread per matrix; each = 8 floats of one row
    int am[2], ak[2];
    #pragma unroll
    for (int i = 0; i < 2; i++) {
        const int idx = t + i * 256;
        am[i] = idx >> 2;
        ak[i] = (idx & 3) << 3;
    }

    float acc[4][4][4];
    #pragma unroll
    for (int mi = 0; mi < 4; mi++)
        #pragma unroll
        for (int nj = 0; nj < 4; nj++)
            #pragma unroll
            for (int e = 0; e < 4; e++)
                acc[mi][nj][e] = 0.f;

    const int nk = K >> 5;

    // ldmatrix address components (stage-base invariant)
    // A: row = wm*64 + mi*16 + (lane&15); kbyte = hilo*64 + ki*32 + (lane>>4)*16
    uint32_t aoff[2][2][4];  // [hilo][ki][mi]
    #pragma unroll
    for (int hl = 0; hl < 2; hl++)
        #pragma unroll
        for (int ki = 0; ki < 2; ki++)
            #pragma unroll
            for (int mi = 0; mi < 4; mi++) {
                const uint32_t row = wm * 64 + mi * 16 + (lane & 15);
                const uint32_t col = hl * 64 + ki * 32 + ((lane >> 4) << 4);
                aoff[hl][ki][mi] = SW128(row * 128 + col);
            }
    // B: row = wn*32 + nx*16 + ((lane>>4)<<3) + (lane&7); kbyte = hilo*64 + ki*32 + ((lane>>3)&1)*16
    uint32_t boff[2][2][2];  // [hilo][ki][nx]
    #pragma unroll
    for (int hl = 0; hl < 2; hl++)
        #pragma unroll
        for (int ki = 0; ki < 2; ki++)
            #pragma unroll
            for (int nx = 0; nx < 2; nx++) {
                const uint32_t row = wn * 32 + nx * 16 + ((lane >> 4) << 3) + (lane & 7);
                const uint32_t col = hl * 64 + ki * 32 + (((lane >> 3) & 1) << 4);
                boff[hl][ki][nx] = SW128(row * 128 + col);
            }

    F8 ra[2], rb[2];
    auto LOAD = [&](int kc) {
        const int kb = kc << 5;
        #pragma unroll
        for (int i = 0; i < 2; i++) {
            const float* ga = A + (size_t)(mBase + am[i]) * K + kb + ak[i];
            ra[i] = ldg8(ga);
            if (A2) {
                const F8 e = ldg8(A2 + (size_t)(mBase + am[i]) * K + kb + ak[i]);
                ra[i].a.x += e.a.x; ra[i].a.y += e.a.y; ra[i].a.z += e.a.z; ra[i].a.w += e.a.w;
                ra[i].b.x += e.b.x; ra[i].b.y += e.b.y; ra[i].b.z += e.b.z; ra[i].b.w += e.b.w;
            }
            rb[i] = ldg8(B + (size_t)(nBase + am[i]) * K + kb + ak[i]);
        }
    };
    auto STORE = [&](int s) {
        const uint32_t sA = sbA + (uint32_t)s * STAGE_BYTES;
        const uint32_t sB = sA + 16384;
        #pragma unroll
        for (int i = 0; i < 2; i++) {
            const uint32_t base = (uint32_t)(am[i] * 128 + ak[i] * 2);
            cvt8_store(sA + SW128(base), sA + SW128(base + 64), ra[i].a, ra[i].b);
            cvt8_store(sB + SW128(base), sB + SW128(base + 64), rb[i].a, rb[i].b);
        }
    };
    auto COMPUTE = [&](int s) {
        const uint32_t sA = sbA + (uint32_t)s * STAGE_BYTES;
        const uint32_t sB = sA + 16384;
        #pragma unroll
        for (int ki = 0; ki < 2; ki++) {
            uint32_t Ah[4][4], Al[4][4], Bh[4][2], Bl[4][2];
            #pragma unroll
            for (int mi = 0; mi < 4; mi++) {
                ldsm4(Ah[mi], sA + aoff[0][ki][mi]);
                ldsm4(Al[mi], sA + aoff[1][ki][mi]);
            }
            #pragma unroll
            for (int nx = 0; nx < 2; nx++) {
                uint32_t th[4], tl[4];
                ldsm4(th, sB + boff[0][ki][nx]);
                ldsm4(tl, sB + boff[1][ki][nx]);
                Bh[nx*2][0] = th[0]; Bh[nx*2][1] = th[1];
                Bh[nx*2+1][0] = th[2]; Bh[nx*2+1][1] = th[3];
                Bl[nx*2][0] = tl[0]; Bl[nx*2][1] = tl[1];
                Bl[nx*2+1][0] = tl[2]; Bl[nx*2+1][1] = tl[3];
            }
            #pragma unroll
            for (int mi = 0; mi < 4; mi++)
                #pragma unroll
                for (int nj = 0; nj < 4; nj++) {
                    mma16816(acc[mi][nj], Ah[mi], Bh[nj][0], Bh[nj][1]);
                    mma16816(acc[mi][nj], Ah[mi], Bl[nj][0], Bl[nj][1]);
                    mma16816(acc[mi][nj], Al[mi], Bh[nj][0], Bh[nj][1]);
                }
        }
    };

    // prologue: fill stage 0
    LOAD(0);
    STORE(0);
    __syncthreads();

    for (int kc = 0; kc < nk; kc++) {
        const int s = kc & 1;
        const bool more = (kc + 1 < nk);
        if (more) LOAD(kc + 1);       // LDG in flight under compute
        COMPUTE(s);
        __syncthreads();              // everyone done reading buf s^1 (prev) & this
        if (more) {
            STORE(s ^ 1);
            __syncthreads();
        }
    }

    // ---- epilogue: regs -> SMEM (pitch 132 floats) -> coalesced float4 stores
    float* epi = (float*)smem;
    const int g  = lane >> 2;
    const int tq = lane & 3;
    #pragma unroll
    for (int mi = 0; mi < 4; mi++) {
        #pragma unroll
        for (int nj = 0; nj < 4; nj++) {
            const int col = wn * 32 + nj * 8 + tq * 2;
            #pragma unroll
            for (int half = 0; half < 2; half++) {
                const int m = wm * 64 + mi * 16 + g + half * 8;
                float v0 = acc[mi][nj][half*2 + 0];
                float v1 = acc[mi][nj][half*2 + 1];
                if (EPI == 2) {
                    v0 = 1.f / (1.f + __expf(-v0 * scale));
                    v1 = 1.f / (1.f + __expf(-v1 * scale));
                } else {
                    if (bias) { v0 += bias[nBase + col]; v1 += bias[nBase + col + 1]; }
                    if (EPI == 1) { v0 = fmaxf(v0, 0.f); v1 = fmaxf(v1, 0.f); }
                }
                if (EPI == 3) {
                    epi[(col)     * EPI_PITCH + m] = v0;
                    epi[(col + 1) * EPI_PITCH + m] = v1;
                } else {
                    epi[m * EPI_PITCH + col]     = v0;
                    epi[m * EPI_PITCH + col + 1] = v1;
                }
            }
        }
    }
    __syncthreads();

    const int r  = t >> 1;
    const int ch = (t & 1) * 64;
    if (EPI == 3) {
        // epi holds tile as [n][m]; write V^T[batch][nGlob][mGlob]
        const size_t boffs = (size_t)(mBase >> 12) * ((size_t)EMB * SEQ);
        float* Cp = C + boffs + (size_t)(nBase + r) * SEQ + (mBase & (SEQ - 1)) + ch;
        #pragma unroll
        for (int i = 0; i < 16; i++) {
            const float* e = &epi[r * EPI_PITCH + ch + i * 4];
            *(float4*)(Cp + i * 4) = make_float4(e[0], e[1], e[2], e[3]);
        }
    } else {
        float* Cp = C + (size_t)(mBase + r) * ldC + nBase + ch;
        #pragma unroll
        for (int i = 0; i < 16; i++) {
            const float* e = &epi[r * EPI_PITCH + ch + i * 4];
            *(float4*)(Cp + i * 4) = make_float4(e[0], e[1], e[2], e[3]);
        }
    }
}

// ---------------- LayerNorm ----------------
__global__ void __launch_bounds__(256)
layernorm_kernel(const float* __restrict__ x, const float* __restrict__ g,
                 const float* __restrict__ b, float* __restrict__ out)
{
    const int row = blockIdx.x;
    const float* xr = x + (size_t)row * EMB;
    float* orow = out + (size_t)row * EMB;
    const int t = threadIdx.x;

    const float4 v = *(const float4*)(xr + t * 4);
    float s  = v.x + v.y + v.z + v.w;
    float ss = v.x * v.x + v.y * v.y + v.z * v.z + v.w * v.w;

    __shared__ float shs[8], shss[8], shmu[1], shinv[1];
    const int lane = t & 31, w = t >> 5;
    #pragma unroll
    for (int o = 16; o > 0; o >>= 1) {
        s  += __shfl_down_sync(0xffffffffu, s,  o);
        ss += __shfl_down_sync(0xffffffffu, ss, o);
    }
    if (lane == 0) { shs[w] = s; shss[w] = ss; }
    __syncthreads();
    if (w == 0) {
        float s2  = (lane < 8) ? shs[lane]  : 0.f;
        float ss2 = (lane < 8) ? shss[lane] : 0.f;
        #pragma unroll
        for (int o = 4; o > 0; o >>= 1) {
            s2  += __shfl_down_sync(0xffffffffu, s2,  o);
            ss2 += __shfl_down_sync(0xffffffffu, ss2, o);
        }
        if (lane == 0) {
            const float mu  = s2 * (1.f / EMB);
            const float var = ss2 * (1.f / EMB) - mu * mu;
            shmu[0]  = mu;
            shinv[0] = rsqrtf(var + 1e-5f);
        }
    }
    __syncthreads();
    const float mu = shmu[0], inv = shinv[0];

    const float4 gv = *(const float4*)(g + t * 4);
    const float4 bv = *(const float4*)(b + t * 4);
    float4 o;
    o.x = (v.x - mu) * inv * gv.x + bv.x;
    o.y = (v.y - mu) * inv * gv.y + bv.y;
    o.z = (v.z - mu) * inv * gv.z + bv.z;
    o.w = (v.w - mu) * inv * gv.w + bv.w;
    *(float4*)(orow + t * 4) = o;
}

// ---------------- launch ----------------
extern "C" void kernel_launch(void* const* d_in, const int* in_sizes, int n_in,
                              void* d_out, int out_size)
{
    const float* value  = (const float*)d_in[0];
    const float* key_t  = (const float*)d_in[1];
    const float* query  = (const float*)d_in[2];
    const float* embed0 = (const float*)d_in[3];
    const float* Wq = (const float*)d_in[4];
    const float* bq = (const float*)d_in[5];
    const float* Wk = (const float*)d_in[6];
    const float* bk = (const float*)d_in[7];
    const float* Wv = (const float*)d_in[8];
    const float* bv = (const float*)d_in[9];
    const float* W1 = (const float*)d_in[10];
    const float* b1 = (const float*)d_in[11];
    const float* W2 = (const float*)d_in[12];
    const float* b2 = (const float*)d_in[13];
    const float* g1  = (const float*)d_in[14];
    const float* be1 = (const float*)d_in[15];
    const float* g2  = (const float*)d_in[16];
    const float* be2 = (const float*)d_in[17];

    float *q, *k, *vt, *x, *h, *y;
    cudaGetSymbolAddress((void**)&q,  g_q);
    cudaGetSymbolAddress((void**)&k,  g_k);
    cudaGetSymbolAddress((void**)&vt, g_vt);
    cudaGetSymbolAddress((void**)&x,  g_x);
    cudaGetSymbolAddress((void**)&h,  g_h);
    cudaGetSymbolAddress((void**)&y,  g_y);

    cudaFuncSetAttribute(hmma_gemm<0>, cudaFuncAttributeMaxDynamicSharedMemorySize, SMEM_TOTAL);
    cudaFuncSetAttribute(hmma_gemm<1>, cudaFuncAttributeMaxDynamicSharedMemorySize, SMEM_TOTAL);
    cudaFuncSetAttribute(hmma_gemm<2>, cudaFuncAttributeMaxDynamicSharedMemorySize, SMEM_TOTAL);
    cudaFuncSetAttribute(hmma_gemm<3>, cudaFuncAttributeMaxDynamicSharedMemorySize, SMEM_TOTAL);

    float* outp = (float*)d_out;
    const long long outElems  = (long long)MROWS * EMB;
    const long long attnElems = (long long)NBATCH * SEQ * SEQ;
    float* attn = ((long long)out_size >= outElems + attnElems) ? (outp + outElems) : h;

    dim3 blk(256);
    const float scale = 1.0f / 32.0f;

    // 1) QKV projections (embed add fused); V writes transposed
    dim3 gQKV(EMB / 128, MROWS / 128, 1);
    hmma_gemm<0><<<gQKV, blk, SMEM_TOTAL>>>(query, embed0, Wq, bq, q,  EMB, EMB, 0, 0, 0, 0.f);
    hmma_gemm<0><<<gQKV, blk, SMEM_TOTAL>>>(key_t, embed0, Wk, bk, k,  EMB, EMB, 0, 0, 0, 0.f);
    hmma_gemm<3><<<gQKV, blk, SMEM_TOTAL>>>(value, embed0, Wv, bv, vt, EMB, EMB, 0, 0, 0, 0.f);

    // 2) attn = sigmoid(q @ k^T * scale), per batch
    dim3 gS(SEQ / 128, SEQ / 128, NBATCH);
    hmma_gemm<2><<<gS, blk, SMEM_TOTAL>>>(q, nullptr, k, nullptr, attn, EMB, SEQ,
                                          (size_t)SEQ * EMB, (size_t)SEQ * EMB, (size_t)SEQ * SEQ, scale);

    // 3) x = attn @ v  (= attn @ (V^T)^T), per batch
    dim3 gAV(EMB / 128, SEQ / 128, NBATCH);
    hmma_gemm<0><<<gAV, blk, SMEM_TOTAL>>>(attn, nullptr, vt, nullptr, x, SEQ, EMB,
                                           (size_t)SEQ * SEQ, (size_t)EMB * SEQ, (size_t)SEQ * EMB, 0.f);

    // 4) LN1 in place
    layernorm_kernel<<<MROWS, 256>>>(x, g1, be1, x);

    // 5) FFN1 = relu(x @ W1^T + b1)
    dim3 gF1(FFDIM / 128, MROWS / 128, 1);
    hmma_gemm<1><<<gF1, blk, SMEM_TOTAL>>>(x, nullptr, W1, b1, h, EMB, FFDIM, 0, 0, 0, 0.f);

    // 6) FFN2 = h @ W2^T + b2
    dim3 gF2(EMB / 128, MROWS / 128, 1);
    hmma_gemm<0><<<gF2, blk, SMEM_TOTAL>>>(h, nullptr, W2, b2, y, FFDIM, EMB, 0, 0, 0, 0.f);

    // 7) LN2 -> out
    layernorm_kernel<<<MROWS, 256>>>(y, g2, be2, outp);
}